// round 1
// baseline (speedup 1.0000x reference)
#include <cuda_runtime.h>
#include <cuda_bf16.h>
#include <math.h>

#define Nn   10000
#define Pp   4
#define Ee   160000
#define INs  256
#define Hh   8
#define Dd   64
#define HDs  512          // H*D
#define PHD  2048         // P*HD

// ---------------- scratch (static device globals; no allocation) ----------------
__device__ float g_Wh[Nn * PHD];          // [n][p*512+c]  82 MB
__device__ float g_z [Nn * PHD];          // [n][p*512+c]  82 MB
__device__ float g_el[Pp * Nn * Hh];
__device__ float g_er[Pp * Nn * Hh];
__device__ float g_e [Pp * Ee * Hh];      // 20.5 MB
__device__ int   g_off[Pp * (Nn + 1)];
__device__ int   g_cur[Pp * Nn];          // deg -> exclusive offsets -> scatter cursor
__device__ int   g_perm[Pp * Ee];
__device__ float g_T  [Nn * Pp * 64];     // tanh(Z@W1+b1)
__device__ float g_scores[Nn * Pp];
__device__ float g_wsum[Pp];
__device__ float g_beta[Pp];

// ---------------- generic 64x64 tiled SGEMM, C[M,*] = A[M,K] @ B[K,*] ----------------
// mode 0: plain.  mode 1: C = tanhf(acc + bias[col])
__global__ void sgemm64(const float* __restrict__ A, const float* __restrict__ B,
                        float* __restrict__ C, const float* __restrict__ bias,
                        int M, int K, int lda, int ldb, int ldc, int colOff, int mode)
{
    __shared__ float As[16][68];
    __shared__ float Bs[16][68];
    const int tid = threadIdx.x;
    const int tx = tid & 15, ty = tid >> 4;
    const int row0 = blockIdx.y * 64, col0 = blockIdx.x * 64;

    const int lm = tid >> 2;           // 0..63 (A row within tile)
    const int lk = (tid & 3) * 4;      // 0,4,8,12 (A k within tile)
    const int bk = tid >> 4;           // 0..15 (B k within tile)
    const int bc = (tid & 15) * 4;     // 0..60 (B col within tile)

    float acc[4][4];
#pragma unroll
    for (int i = 0; i < 4; i++)
#pragma unroll
        for (int j = 0; j < 4; j++) acc[i][j] = 0.f;

    for (int kt = 0; kt < K; kt += 16) {
        float4 a4 = make_float4(0.f, 0.f, 0.f, 0.f);
        int r = row0 + lm;
        if (r < M) a4 = *(const float4*)&A[(size_t)r * lda + kt + lk];
        As[lk + 0][lm] = a4.x; As[lk + 1][lm] = a4.y;
        As[lk + 2][lm] = a4.z; As[lk + 3][lm] = a4.w;

        float4 b4 = *(const float4*)&B[(size_t)(kt + bk) * ldb + col0 + bc];
        *(float4*)&Bs[bk][bc] = b4;
        __syncthreads();

#pragma unroll
        for (int k = 0; k < 16; k++) {
            float4 av = *(const float4*)&As[k][ty * 4];
            float4 bv = *(const float4*)&Bs[k][tx * 4];
            float a[4] = {av.x, av.y, av.z, av.w};
            float b[4] = {bv.x, bv.y, bv.z, bv.w};
#pragma unroll
            for (int i = 0; i < 4; i++)
#pragma unroll
                for (int j = 0; j < 4; j++) acc[i][j] += a[i] * b[j];
        }
        __syncthreads();
    }

#pragma unroll
    for (int i = 0; i < 4; i++) {
        int r = row0 + ty * 4 + i;
        if (r >= M) continue;
        float vv[4];
#pragma unroll
        for (int j = 0; j < 4; j++) {
            float t = acc[i][j];
            if (mode == 1) t = tanhf(t + bias[col0 + tx * 4 + j]);
            vv[j] = t;
        }
        float4 v = make_float4(vv[0], vv[1], vv[2], vv[3]);
        *(float4*)&C[(size_t)r * ldc + colOff + col0 + tx * 4] = v;
    }
}

// ---------------- el/er: per (p,n,h) dot of Wh row-slice with attn vectors ----------------
__global__ void compute_lr(const float* __restrict__ attn_l, const float* __restrict__ attn_r)
{
    int idx = blockIdx.x * blockDim.x + threadIdx.x;   // idx = (p*N+n)*8 + h
    if (idx >= Pp * Nn * Hh) return;
    int h = idx & 7;
    int n = (idx >> 3) % Nn;
    int p = idx / (Nn * Hh);
    const float4* w  = (const float4*)(g_Wh + (size_t)n * PHD + p * HDs + h * Dd);
    const float4* al = (const float4*)(attn_l + (p * Hh + h) * Dd);
    const float4* ar = (const float4*)(attn_r + (p * Hh + h) * Dd);
    float sl = 0.f, sr = 0.f;
#pragma unroll
    for (int i = 0; i < 16; i++) {
        float4 wv = w[i], a = al[i], b = ar[i];
        sl += wv.x * a.x + wv.y * a.y + wv.z * a.z + wv.w * a.w;
        sr += wv.x * b.x + wv.y * b.y + wv.z * b.z + wv.w * b.w;
    }
    g_el[idx] = sl;
    g_er[idx] = sr;
}

// ---------------- CSR build ----------------
__global__ void zero_cur_k()
{
    int idx = blockIdx.x * blockDim.x + threadIdx.x;
    if (idx < Pp * Nn) g_cur[idx] = 0;
}

__global__ void hist_k(const int* __restrict__ edst)
{
    int idx = blockIdx.x * blockDim.x + threadIdx.x;
    if (idx >= Pp * Ee) return;
    int p = idx / Ee;
    atomicAdd(&g_cur[p * Nn + edst[idx]], 1);
}

__global__ void scan_k()
{
    __shared__ int sh[1024];
    int p = blockIdx.x, tid = threadIdx.x;
    int base = 0;
    for (int c0 = 0; c0 < Nn; c0 += 1024) {
        int i = c0 + tid;
        int v = (i < Nn) ? g_cur[p * Nn + i] : 0;
        sh[tid] = v;
        __syncthreads();
        for (int ofs = 1; ofs < 1024; ofs <<= 1) {
            int t = (tid >= ofs) ? sh[tid - ofs] : 0;
            __syncthreads();
            sh[tid] += t;
            __syncthreads();
        }
        int incl = sh[tid];
        if (i < Nn) {
            g_cur[p * Nn + i] = base + incl - v;              // exclusive
            g_off[p * (Nn + 1) + i + 1] = base + incl;
        }
        if (i == 0) g_off[p * (Nn + 1)] = 0;
        base += sh[1023];
        __syncthreads();
    }
}

__global__ void scatter_k(const int* __restrict__ edst)
{
    int idx = blockIdx.x * blockDim.x + threadIdx.x;
    if (idx >= Pp * Ee) return;
    int p = idx / Ee;
    int d = edst[idx];
    int pos = atomicAdd(&g_cur[p * Nn + d], 1);
    g_perm[p * Ee + pos] = idx - p * Ee;
}

// ---------------- per-edge pre-activation e = lrelu(el[src]+er[dst]) ----------------
__global__ void edge_e_k(const int* __restrict__ esrc, const int* __restrict__ edst)
{
    int idx = blockIdx.x * blockDim.x + threadIdx.x;
    if (idx >= Pp * Ee) return;
    int p = idx / Ee;
    int s = esrc[idx], d = edst[idx];
    const float* el = g_el + (size_t)(p * Nn + s) * 8;
    const float* er = g_er + (size_t)(p * Nn + d) * 8;
    float* out = g_e + (size_t)idx * 8;
#pragma unroll
    for (int h = 0; h < 8; h++) {
        float v = el[h] + er[h];
        out[h] = v > 0.f ? v : 0.2f * v;
    }
}

// ---------------- warp-per-dst softmax + aggregation + elu ----------------
__global__ void attn_agg_k(const int* __restrict__ esrc, const float* __restrict__ gat_b)
{
    const int warpsPerBlock = blockDim.x >> 5;
    const int gw = blockIdx.x * warpsPerBlock + (threadIdx.x >> 5);
    if (gw >= Pp * Nn) return;
    const int lane = threadIdx.x & 31;
    const int p = gw / Nn, n = gw % Nn;
    const int beg = g_off[p * (Nn + 1) + n];
    const int end = g_off[p * (Nn + 1) + n + 1];
    const int sub = lane & 7, grp = lane >> 3;
    const int* perm = g_perm + (size_t)p * Ee;
    const float* eb = g_e + (size_t)p * Ee * 8;

    // pass 1: per-head max (4 edges in parallel, 8 lanes/edge)
    float m = -1e30f;
    for (int k = beg + grp; k < end; k += 4) {
        int eid = perm[k];
        m = fmaxf(m, eb[(size_t)eid * 8 + sub]);
    }
    m = fmaxf(m, __shfl_xor_sync(0xffffffffu, m, 8));
    m = fmaxf(m, __shfl_xor_sync(0xffffffffu, m, 16));

    // pass 2: per-head sum of exp
    float s = 0.f;
    for (int k = beg + grp; k < end; k += 4) {
        int eid = perm[k];
        s += expf(eb[(size_t)eid * 8 + sub] - m);
    }
    s += __shfl_xor_sync(0xffffffffu, s, 8);
    s += __shfl_xor_sync(0xffffffffu, s, 16);
    float inv = (s > 0.f) ? 1.f / s : 0.f;

    // pass 3: weighted gather of Wh[src]
    float acc[16];
#pragma unroll
    for (int j = 0; j < 16; j++) acc[j] = 0.f;

    for (int k = beg; k < end; ++k) {
        int eid = perm[k];
        int src = esrc[p * Ee + eid];
        float a8 = 0.f;
        if (lane < 8) a8 = expf(eb[(size_t)eid * 8 + lane] - m) * inv;  // m,inv in lanes 0..7 == their head
        const float* wr = g_Wh + (size_t)src * PHD + p * HDs;
#pragma unroll
        for (int j = 0; j < 16; j++) {
            float a = __shfl_sync(0xffffffffu, a8, (lane + 32 * j) >> 6);
            acc[j] += a * wr[lane + 32 * j];
        }
    }

    // epilogue: + bias, elu, write z
    float* zr = g_z + (size_t)n * PHD + p * HDs;
    const float* br = gat_b + p * HDs;
#pragma unroll
    for (int j = 0; j < 16; j++) {
        int col = lane + 32 * j;
        float v = acc[j] + br[col];
        v = v > 0.f ? v : expm1f(v);
        zr[col] = v;
    }
}

// ---------------- semantic attention tail ----------------
__global__ void score_k(const float* __restrict__ W2)
{
    int gw = blockIdx.x * (blockDim.x >> 5) + (threadIdx.x >> 5);
    if (gw >= Nn * Pp) return;
    int lane = threadIdx.x & 31;
    float v = g_T[(size_t)gw * 64 + lane] * W2[lane] +
              g_T[(size_t)gw * 64 + lane + 32] * W2[lane + 32];
#pragma unroll
    for (int ofs = 16; ofs > 0; ofs >>= 1)
        v += __shfl_xor_sync(0xffffffffu, v, ofs);
    if (lane == 0) g_scores[gw] = v;
}

__global__ void reduce_k()
{
    __shared__ float sh[256];
    int p = blockIdx.x, tid = threadIdx.x;
    float s = 0.f;
    for (int n = tid; n < Nn; n += 256) s += g_scores[(size_t)n * Pp + p];
    sh[tid] = s;
    __syncthreads();
    for (int ofs = 128; ofs > 0; ofs >>= 1) {
        if (tid < ofs) sh[tid] += sh[tid + ofs];
        __syncthreads();
    }
    if (tid == 0) g_wsum[p] = sh[0];
}

__global__ void beta_k()
{
    if (threadIdx.x == 0 && blockIdx.x == 0) {
        float w[Pp], mx = -1e30f;
        for (int p = 0; p < Pp; p++) { w[p] = g_wsum[p] / (float)Nn; mx = fmaxf(mx, w[p]); }
        float ssum = 0.f;
        for (int p = 0; p < Pp; p++) { w[p] = expf(w[p] - mx); ssum += w[p]; }
        for (int p = 0; p < Pp; p++) g_beta[p] = w[p] / ssum;
    }
}

__global__ void combine_k(float* __restrict__ out)
{
    int idx = blockIdx.x * blockDim.x + threadIdx.x;  // float4 index
    if (idx >= Nn * HDs / 4) return;
    int n = idx / (HDs / 4);
    int c4 = (idx % (HDs / 4)) * 4;
    float b0 = g_beta[0], b1 = g_beta[1], b2 = g_beta[2], b3 = g_beta[3];
    const float* zr = g_z + (size_t)n * PHD;
    float4 v0 = *(const float4*)&zr[0 * HDs + c4];
    float4 v1 = *(const float4*)&zr[1 * HDs + c4];
    float4 v2 = *(const float4*)&zr[2 * HDs + c4];
    float4 v3 = *(const float4*)&zr[3 * HDs + c4];
    float4 o;
    o.x = b0 * v0.x + b1 * v1.x + b2 * v2.x + b3 * v3.x;
    o.y = b0 * v0.y + b1 * v1.y + b2 * v2.y + b3 * v3.y;
    o.z = b0 * v0.z + b1 * v1.z + b2 * v2.z + b3 * v3.z;
    o.w = b0 * v0.w + b1 * v1.w + b2 * v2.w + b3 * v3.w;
    *(float4*)&((float*)out)[(size_t)n * HDs + c4] = o;
}

// ---------------- launch ----------------
extern "C" void kernel_launch(void* const* d_in, const int* in_sizes, int n_in,
                              void* d_out, int out_size)
{
    const float* h        = (const float*)d_in[0];   // [N, IN]
    const int*   edge_src = (const int*)  d_in[1];   // [P, E]
    const int*   edge_dst = (const int*)  d_in[2];   // [P, E]
    const float* gat_W    = (const float*)d_in[3];   // [P, IN, HD]
    const float* attn_l   = (const float*)d_in[4];   // [P, H, D]
    const float* attn_r   = (const float*)d_in[5];   // [P, H, D]
    const float* gat_b    = (const float*)d_in[6];   // [P, HD]
    const float* sem_W1   = (const float*)d_in[7];   // [HD, 64]
    const float* sem_b1   = (const float*)d_in[8];   // [64]
    const float* sem_W2   = (const float*)d_in[9];   // [64]
    float* out = (float*)d_out;

    void *pWh, *pZ, *pT;
    cudaGetSymbolAddress(&pWh, g_Wh);
    cudaGetSymbolAddress(&pZ,  g_z);
    cudaGetSymbolAddress(&pT,  g_T);

    // 1) Wh[p] = h @ gat_W[p]   -> g_Wh [n][p*512+c]
    for (int p = 0; p < Pp; p++) {
        sgemm64<<<dim3(HDs / 64, (Nn + 63) / 64), 256>>>(
            h, gat_W + (size_t)p * INs * HDs, (float*)pWh, nullptr,
            Nn, INs, INs, HDs, PHD, p * HDs, 0);
    }

    // 2) el/er
    compute_lr<<<(Pp * Nn * Hh + 255) / 256, 256>>>(attn_l, attn_r);

    // 3) CSR build (independent of GEMM; stream order serializes anyway)
    zero_cur_k<<<(Pp * Nn + 255) / 256, 256>>>();
    hist_k<<<(Pp * Ee + 255) / 256, 256>>>(edge_dst);
    scan_k<<<Pp, 1024>>>();
    scatter_k<<<(Pp * Ee + 255) / 256, 256>>>(edge_dst);

    // 4) per-edge attention logits
    edge_e_k<<<(Pp * Ee + 255) / 256, 256>>>(edge_src, edge_dst);

    // 5) softmax + aggregate + elu -> g_z
    attn_agg_k<<<(Pp * Nn + 7) / 8, 256>>>(edge_src, gat_b);

    // 6) T = tanh(Z @ W1 + b1), Z = g_z viewed as [N*P, 512]
    sgemm64<<<dim3(1, (Nn * Pp + 63) / 64), 256>>>(
        (const float*)pZ, sem_W1, (float*)pT, sem_b1,
        Nn * Pp, HDs, HDs, 64, 64, 0, 1);

    // 7) scores, per-path mean, softmax, combine
    score_k<<<(Nn * Pp + 7) / 8, 256>>>(sem_W2);
    reduce_k<<<Pp, 256>>>();
    beta_k<<<1, 32>>>();
    combine_k<<<(Nn * HDs / 4 + 255) / 256, 256>>>(out);
}

// round 2
// speedup vs baseline: 1.0852x; 1.0852x over previous
#include <cuda_runtime.h>
#include <cuda_bf16.h>
#include <math.h>

#define Nn   10000
#define Pp   4
#define Ee   160000
#define INs  256
#define Hh   8
#define Dd   64
#define HDs  512          // H*D
#define PHD  2048         // P*HD

// ---------------- scratch (static device globals; no allocation) ----------------
__device__ float g_Wh[Nn * PHD];          // [n][p*512+c]
__device__ float g_z [Nn * PHD];          // [n][p*512+c]
__device__ float g_el[Pp * Nn * Hh];
__device__ float g_er[Pp * Nn * Hh];
__device__ float g_e [Pp * Ee * Hh];      // logits, then exp(e-m)
__device__ int   g_off[Pp * (Nn + 1)];
__device__ int   g_cur[Pp * Nn];
__device__ int   g_perm[Pp * Ee];
__device__ float g_T  [Nn * Pp * 64];
__device__ float g_scores[Nn * Pp];
__device__ float g_wsum[Pp];
__device__ float g_beta[Pp];

// ---------------- 128xTN tiled SGEMM, 8x(TN/16) micro-tile ----------------
// C[r, z*cColStride + col] = A[M,K] @ B(z)[K,TN-block]
// MODE 0: plain.  MODE 1: C = tanh(acc + bias[col])
template<int TN, int MODE>
__global__ __launch_bounds__(256)
void sgemm_t(const float* __restrict__ A, const float* __restrict__ B0,
             float* __restrict__ C, const float* __restrict__ bias,
             int M, int K, int lda, int ldb, int ldc,
             long bStride, int cColStride)
{
    constexpr int MICRO_N = TN / 16;      // 8 or 4
    __shared__ float As[8][132];          // transposed A tile, padded
    __shared__ float Bs[8][TN];

    const int tid = threadIdx.x;
    const float* B = B0 + (size_t)blockIdx.z * bStride;
    const int row0 = blockIdx.y * 128;
    const int col0 = blockIdx.x * TN;
    const int ccol0 = blockIdx.z * cColStride + col0;

    // A tile load: 128 rows x 8 k, one float4 per thread
    const int arow = tid >> 1;            // 0..127
    const int ak   = (tid & 1) * 4;       // 0 or 4
    // B tile load: 8 k-rows x TN cols
    const int bk   = tid / (TN / 4);
    const int bc   = (tid % (TN / 4)) * 4;

    const int tx = tid & 15, ty = tid >> 4;

    float acc[8][MICRO_N];
#pragma unroll
    for (int i = 0; i < 8; i++)
#pragma unroll
        for (int j = 0; j < MICRO_N; j++) acc[i][j] = 0.f;

    const int r = row0 + arow;
    const bool aOk = (r < M);

    for (int kt = 0; kt < K; kt += 8) {
        float4 a4 = make_float4(0.f, 0.f, 0.f, 0.f);
        if (aOk) a4 = *(const float4*)&A[(size_t)r * lda + kt + ak];
        As[ak + 0][arow] = a4.x; As[ak + 1][arow] = a4.y;
        As[ak + 2][arow] = a4.z; As[ak + 3][arow] = a4.w;

        if (TN == 128 || bk < 8)
            *(float4*)&Bs[bk][bc] = *(const float4*)&B[(size_t)(kt + bk) * ldb + col0 + bc];
        __syncthreads();

#pragma unroll
        for (int k = 0; k < 8; k++) {
            float4 a0 = *(const float4*)&As[k][ty * 8];
            float4 a1 = *(const float4*)&As[k][ty * 8 + 4];
            float av[8] = {a0.x, a0.y, a0.z, a0.w, a1.x, a1.y, a1.z, a1.w};
            float bv[MICRO_N];
            float4 bb0 = *(const float4*)&Bs[k][tx * 4];
            bv[0] = bb0.x; bv[1] = bb0.y; bv[2] = bb0.z; bv[3] = bb0.w;
            if (MICRO_N == 8) {
                float4 bb1 = *(const float4*)&Bs[k][64 + tx * 4];
                bv[4] = bb1.x; bv[5] = bb1.y; bv[6] = bb1.z; bv[7] = bb1.w;
            }
#pragma unroll
            for (int i = 0; i < 8; i++)
#pragma unroll
                for (int j = 0; j < MICRO_N; j++)
                    acc[i][j] += av[i] * bv[j];
        }
        __syncthreads();
    }

#pragma unroll
    for (int i = 0; i < 8; i++) {
        int rr = row0 + ty * 8 + i;
        if (rr >= M) continue;
        {
            float v0 = acc[i][0], v1 = acc[i][1], v2 = acc[i][2], v3 = acc[i][3];
            if (MODE == 1) {
                int c = col0 + tx * 4;
                v0 = tanhf(v0 + bias[c + 0]); v1 = tanhf(v1 + bias[c + 1]);
                v2 = tanhf(v2 + bias[c + 2]); v3 = tanhf(v3 + bias[c + 3]);
            }
            *(float4*)&C[(size_t)rr * ldc + ccol0 + tx * 4] = make_float4(v0, v1, v2, v3);
        }
        if (MICRO_N == 8) {
            float v0 = acc[i][4], v1 = acc[i][5], v2 = acc[i][6], v3 = acc[i][7];
            if (MODE == 1) {
                int c = col0 + 64 + tx * 4;
                v0 = tanhf(v0 + bias[c + 0]); v1 = tanhf(v1 + bias[c + 1]);
                v2 = tanhf(v2 + bias[c + 2]); v3 = tanhf(v3 + bias[c + 3]);
            }
            *(float4*)&C[(size_t)rr * ldc + ccol0 + 64 + tx * 4] = make_float4(v0, v1, v2, v3);
        }
    }
}

// ---------------- el/er: per (p,n,h) dot of Wh row-slice with attn vectors ----------------
__global__ void compute_lr(const float* __restrict__ attn_l, const float* __restrict__ attn_r)
{
    int idx = blockIdx.x * blockDim.x + threadIdx.x;   // idx = (p*N+n)*8 + h
    if (idx >= Pp * Nn * Hh) return;
    int h = idx & 7;
    int n = (idx >> 3) % Nn;
    int p = idx / (Nn * Hh);
    const float4* w  = (const float4*)(g_Wh + (size_t)n * PHD + p * HDs + h * Dd);
    const float4* al = (const float4*)(attn_l + (p * Hh + h) * Dd);
    const float4* ar = (const float4*)(attn_r + (p * Hh + h) * Dd);
    float sl = 0.f, sr = 0.f;
#pragma unroll
    for (int i = 0; i < 16; i++) {
        float4 wv = w[i], a = al[i], b = ar[i];
        sl += wv.x * a.x + wv.y * a.y + wv.z * a.z + wv.w * a.w;
        sr += wv.x * b.x + wv.y * b.y + wv.z * b.z + wv.w * b.w;
    }
    g_el[idx] = sl;
    g_er[idx] = sr;
}

// ---------------- CSR build ----------------
__global__ void zero_cur_k()
{
    int idx = blockIdx.x * blockDim.x + threadIdx.x;
    if (idx < Pp * Nn) g_cur[idx] = 0;
}

__global__ void hist_k(const int* __restrict__ edst)
{
    int idx = blockIdx.x * blockDim.x + threadIdx.x;
    if (idx >= Pp * Ee) return;
    int p = idx / Ee;
    atomicAdd(&g_cur[p * Nn + edst[idx]], 1);
}

__global__ void scan_k()
{
    __shared__ int sh[1024];
    int p = blockIdx.x, tid = threadIdx.x;
    int base = 0;
    for (int c0 = 0; c0 < Nn; c0 += 1024) {
        int i = c0 + tid;
        int v = (i < Nn) ? g_cur[p * Nn + i] : 0;
        sh[tid] = v;
        __syncthreads();
        for (int ofs = 1; ofs < 1024; ofs <<= 1) {
            int t = (tid >= ofs) ? sh[tid - ofs] : 0;
            __syncthreads();
            sh[tid] += t;
            __syncthreads();
        }
        int incl = sh[tid];
        if (i < Nn) {
            g_cur[p * Nn + i] = base + incl - v;              // exclusive
            g_off[p * (Nn + 1) + i + 1] = base + incl;
        }
        if (i == 0) g_off[p * (Nn + 1)] = 0;
        base += sh[1023];
        __syncthreads();
    }
}

__global__ void scatter_k(const int* __restrict__ edst)
{
    int idx = blockIdx.x * blockDim.x + threadIdx.x;
    if (idx >= Pp * Ee) return;
    int p = idx / Ee;
    int d = edst[idx];
    int pos = atomicAdd(&g_cur[p * Nn + d], 1);
    g_perm[p * Ee + pos] = idx - p * Ee;
}

// ---------------- warp-per-dst: logits + softmax + aggregation + elu ----------------
__global__ void attn_agg_k(const int* __restrict__ esrc, const float* __restrict__ gat_b)
{
    const int warpsPerBlock = blockDim.x >> 5;
    const int gw = blockIdx.x * warpsPerBlock + (threadIdx.x >> 5);
    if (gw >= Pp * Nn) return;
    const int lane = threadIdx.x & 31;
    const int p = gw / Nn, n = gw % Nn;
    const int beg = g_off[p * (Nn + 1) + n];
    const int end = g_off[p * (Nn + 1) + n + 1];
    const int sub = lane & 7, grp = lane >> 3;
    const int* perm   = g_perm + (size_t)p * Ee;
    const int* srcArr = esrc + (size_t)p * Ee;
    const float* el   = g_el + (size_t)p * Nn * 8;
    float* eb         = g_e  + (size_t)p * Ee * 8;

    const float erh = g_er[(size_t)(p * Nn + n) * 8 + sub];   // warp-constant per head

    // pass 1: compute logits on the fly, write to g_e, track per-head max
    float m = -1e30f;
    for (int k = beg + grp; k < end; k += 4) {
        int eid = perm[k];
        int s = srcArr[eid];
        float v = el[(size_t)s * 8 + sub] + erh;
        v = v > 0.f ? v : 0.2f * v;
        eb[(size_t)eid * 8 + sub] = v;
        m = fmaxf(m, v);
    }
    m = fmaxf(m, __shfl_xor_sync(0xffffffffu, m, 8));
    m = fmaxf(m, __shfl_xor_sync(0xffffffffu, m, 16));

    // pass 2: exp, cache ex back into g_e, per-head sum
    float s = 0.f;
    for (int k = beg + grp; k < end; k += 4) {
        size_t a = (size_t)perm[k] * 8 + sub;
        float ex = expf(eb[a] - m);
        eb[a] = ex;
        s += ex;
    }
    s += __shfl_xor_sync(0xffffffffu, s, 8);
    s += __shfl_xor_sync(0xffffffffu, s, 16);
    float inv = (s > 0.f) ? 1.f / s : 0.f;
    __syncwarp();

    // pass 3: weighted gather of Wh[src]
    float acc[16];
#pragma unroll
    for (int j = 0; j < 16; j++) acc[j] = 0.f;

    for (int k = beg; k < end; ++k) {
        int eid = perm[k];
        int src = srcArr[eid];
        float a8 = 0.f;
        if (lane < 8) a8 = eb[(size_t)eid * 8 + lane] * inv;
        const float* wr = g_Wh + (size_t)src * PHD + p * HDs;
#pragma unroll
        for (int j = 0; j < 16; j++) {
            float a = __shfl_sync(0xffffffffu, a8, (lane + 32 * j) >> 6);
            acc[j] += a * wr[lane + 32 * j];
        }
    }

    // epilogue: + bias, elu, write z
    float* zr = g_z + (size_t)n * PHD + p * HDs;
    const float* br = gat_b + p * HDs;
#pragma unroll
    for (int j = 0; j < 16; j++) {
        int col = lane + 32 * j;
        float v = acc[j] + br[col];
        v = v > 0.f ? v : expm1f(v);
        zr[col] = v;
    }
}

// ---------------- semantic attention tail ----------------
__global__ void score_k(const float* __restrict__ W2)
{
    int gw = blockIdx.x * (blockDim.x >> 5) + (threadIdx.x >> 5);
    if (gw >= Nn * Pp) return;
    int lane = threadIdx.x & 31;
    float v = g_T[(size_t)gw * 64 + lane] * W2[lane] +
              g_T[(size_t)gw * 64 + lane + 32] * W2[lane + 32];
#pragma unroll
    for (int ofs = 16; ofs > 0; ofs >>= 1)
        v += __shfl_xor_sync(0xffffffffu, v, ofs);
    if (lane == 0) g_scores[gw] = v;
}

__global__ void reduce_k()
{
    __shared__ float sh[256];
    int p = blockIdx.x, tid = threadIdx.x;
    float s = 0.f;
    for (int n = tid; n < Nn; n += 256) s += g_scores[(size_t)n * Pp + p];
    sh[tid] = s;
    __syncthreads();
    for (int ofs = 128; ofs > 0; ofs >>= 1) {
        if (tid < ofs) sh[tid] += sh[tid + ofs];
        __syncthreads();
    }
    if (tid == 0) g_wsum[p] = sh[0];
}

__global__ void beta_k()
{
    if (threadIdx.x == 0 && blockIdx.x == 0) {
        float w[Pp], mx = -1e30f;
        for (int p = 0; p < Pp; p++) { w[p] = g_wsum[p] / (float)Nn; mx = fmaxf(mx, w[p]); }
        float ssum = 0.f;
        for (int p = 0; p < Pp; p++) { w[p] = expf(w[p] - mx); ssum += w[p]; }
        for (int p = 0; p < Pp; p++) g_beta[p] = w[p] / ssum;
    }
}

__global__ void combine_k(float* __restrict__ out)
{
    int idx = blockIdx.x * blockDim.x + threadIdx.x;  // float4 index
    if (idx >= Nn * HDs / 4) return;
    int n = idx / (HDs / 4);
    int c4 = (idx % (HDs / 4)) * 4;
    float b0 = g_beta[0], b1 = g_beta[1], b2 = g_beta[2], b3 = g_beta[3];
    const float* zr = g_z + (size_t)n * PHD;
    float4 v0 = *(const float4*)&zr[0 * HDs + c4];
    float4 v1 = *(const float4*)&zr[1 * HDs + c4];
    float4 v2 = *(const float4*)&zr[2 * HDs + c4];
    float4 v3 = *(const float4*)&zr[3 * HDs + c4];
    float4 o;
    o.x = b0 * v0.x + b1 * v1.x + b2 * v2.x + b3 * v3.x;
    o.y = b0 * v0.y + b1 * v1.y + b2 * v2.y + b3 * v3.y;
    o.z = b0 * v0.z + b1 * v1.z + b2 * v2.z + b3 * v3.z;
    o.w = b0 * v0.w + b1 * v1.w + b2 * v2.w + b3 * v3.w;
    *(float4*)&((float*)out)[(size_t)n * HDs + c4] = o;
}

// ---------------- launch ----------------
extern "C" void kernel_launch(void* const* d_in, const int* in_sizes, int n_in,
                              void* d_out, int out_size)
{
    const float* h        = (const float*)d_in[0];   // [N, IN]
    const int*   edge_src = (const int*)  d_in[1];   // [P, E]
    const int*   edge_dst = (const int*)  d_in[2];   // [P, E]
    const float* gat_W    = (const float*)d_in[3];   // [P, IN, HD]
    const float* attn_l   = (const float*)d_in[4];   // [P, H, D]
    const float* attn_r   = (const float*)d_in[5];   // [P, H, D]
    const float* gat_b    = (const float*)d_in[6];   // [P, HD]
    const float* sem_W1   = (const float*)d_in[7];   // [HD, 64]
    const float* sem_b1   = (const float*)d_in[8];   // [64]
    const float* sem_W2   = (const float*)d_in[9];   // [64]
    float* out = (float*)d_out;

    void *pWh, *pZ, *pT;
    cudaGetSymbolAddress(&pWh, g_Wh);
    cudaGetSymbolAddress(&pZ,  g_z);
    cudaGetSymbolAddress(&pT,  g_T);

    // CSR build (cheap int work first; also overlaps GEMM tail in-order anyway)
    zero_cur_k<<<(Pp * Nn + 255) / 256, 256>>>();
    hist_k<<<(Pp * Ee + 255) / 256, 256>>>(edge_dst);
    scan_k<<<Pp, 1024>>>();
    scatter_k<<<(Pp * Ee + 255) / 256, 256>>>(edge_dst);

    // 1) Wh[p] = h @ gat_W[p] for all p in one launch
    sgemm_t<128, 0><<<dim3(HDs / 128, (Nn + 127) / 128, Pp), 256>>>(
        h, gat_W, (float*)pWh, nullptr,
        Nn, INs, INs, HDs, PHD, (long)INs * HDs, HDs);

    // 2) el/er
    compute_lr<<<(Pp * Nn * Hh + 255) / 256, 256>>>(attn_l, attn_r);

    // 3) logits + softmax + aggregate + elu -> g_z
    attn_agg_k<<<(Pp * Nn + 7) / 8, 256>>>(edge_src, gat_b);

    // 4) T = tanh(Z @ W1 + b1), Z = g_z viewed as [N*P, 512]
    sgemm_t<64, 1><<<dim3(1, (Nn * Pp + 127) / 128, 1), 256>>>(
        (const float*)pZ, sem_W1, (float*)pT, sem_b1,
        Nn * Pp, HDs, HDs, 64, 64, 0L, 0);

    // 5) scores, per-path mean, softmax, combine
    score_k<<<(Nn * Pp + 7) / 8, 256>>>(sem_W2);
    reduce_k<<<Pp, 256>>>();
    beta_k<<<1, 32>>>();
    combine_k<<<(Nn * HDs / 4 + 255) / 256, 256>>>(out);
}

// round 3
// speedup vs baseline: 1.1646x; 1.0731x over previous
#include <cuda_runtime.h>
#include <cuda_bf16.h>
#include <math.h>

#define Nn   10000
#define Pp   4
#define Ee   160000
#define INs  256
#define Hh   8
#define Dd   64
#define HDs  512          // H*D
#define PHD  2048         // P*HD

// ---------------- scratch (static device globals; no allocation) ----------------
__device__ float g_Wh[Nn * PHD];          // [n][p*512+c]
__device__ float g_z [Nn * PHD];          // [n][p*512+c]
__device__ float g_el[Pp * Nn * Hh];
__device__ float g_er[Pp * Nn * Hh];
__device__ int   g_off[Pp * (Nn + 1)];
__device__ int   g_cur[Pp * Nn];
__device__ int   g_srcs[Pp * Ee];         // src ids sorted by dst (CSR payload)
__device__ float g_T  [Nn * Pp * 64];
__device__ float g_scores[Nn * Pp];
__device__ float g_wsum[Pp];
__device__ float g_beta[Pp];

// ---------------- 128xTN tiled SGEMM, double-buffered, 8x(TN/16) micro-tile ----------------
// MODE 0: plain.  MODE 1: C = tanh(acc + bias[col])
template<int TN, int MODE>
__global__ __launch_bounds__(256, 2)
void sgemm_t(const float* __restrict__ A, const float* __restrict__ B0,
             float* __restrict__ C, const float* __restrict__ bias,
             int M, int K, int lda, int ldb, int ldc,
             long bStride, int cColStride)
{
    constexpr int MICRO_N = TN / 16;      // 8 or 4
    __shared__ float As[2][8][132];
    __shared__ float Bs[2][8][TN];

    const int tid = threadIdx.x;
    const float* B = B0 + (size_t)blockIdx.z * bStride;
    const int row0 = blockIdx.y * 128;
    const int col0 = blockIdx.x * TN;
    const int ccol0 = blockIdx.z * cColStride + col0;

    const int arow = tid >> 1;            // 0..127
    const int ak   = (tid & 1) * 4;       // 0 or 4
    const int bk   = tid / (TN / 4);
    const int bc   = (tid % (TN / 4)) * 4;
    const bool bOk = (TN == 128) || (bk < 8);

    const int tx = tid & 15, ty = tid >> 4;

    float acc[8][MICRO_N];
#pragma unroll
    for (int i = 0; i < 8; i++)
#pragma unroll
        for (int j = 0; j < MICRO_N; j++) acc[i][j] = 0.f;

    const int r = row0 + arow;
    const bool aOk = (r < M);

    // preload tile 0
    {
        float4 a4 = make_float4(0.f, 0.f, 0.f, 0.f);
        if (aOk) a4 = *(const float4*)&A[(size_t)r * lda + ak];
        As[0][ak + 0][arow] = a4.x; As[0][ak + 1][arow] = a4.y;
        As[0][ak + 2][arow] = a4.z; As[0][ak + 3][arow] = a4.w;
        if (bOk)
            *(float4*)&Bs[0][bk][bc] = *(const float4*)&B[(size_t)bk * ldb + col0 + bc];
    }
    __syncthreads();

    const int nT = K / 8;
    for (int t = 0; t < nT; t++) {
        const int cur = t & 1;
        float4 a4n = make_float4(0.f, 0.f, 0.f, 0.f), b4n;
        const bool more = (t + 1 < nT);
        if (more) {
            int kt = (t + 1) * 8;
            if (aOk) a4n = *(const float4*)&A[(size_t)r * lda + kt + ak];
            if (bOk) b4n = *(const float4*)&B[(size_t)(kt + bk) * ldb + col0 + bc];
        }

#pragma unroll
        for (int k = 0; k < 8; k++) {
            float4 a0 = *(const float4*)&As[cur][k][ty * 8];
            float4 a1 = *(const float4*)&As[cur][k][ty * 8 + 4];
            float av[8] = {a0.x, a0.y, a0.z, a0.w, a1.x, a1.y, a1.z, a1.w};
            float bv[MICRO_N];
            float4 bb0 = *(const float4*)&Bs[cur][k][tx * 4];
            bv[0] = bb0.x; bv[1] = bb0.y; bv[2] = bb0.z; bv[3] = bb0.w;
            if (MICRO_N == 8) {
                float4 bb1 = *(const float4*)&Bs[cur][k][64 + tx * 4];
                bv[4] = bb1.x; bv[5] = bb1.y; bv[6] = bb1.z; bv[7] = bb1.w;
            }
#pragma unroll
            for (int i = 0; i < 8; i++)
#pragma unroll
                for (int j = 0; j < MICRO_N; j++)
                    acc[i][j] += av[i] * bv[j];
        }

        if (more) {
            const int nxt = cur ^ 1;
            As[nxt][ak + 0][arow] = a4n.x; As[nxt][ak + 1][arow] = a4n.y;
            As[nxt][ak + 2][arow] = a4n.z; As[nxt][ak + 3][arow] = a4n.w;
            if (bOk) *(float4*)&Bs[nxt][bk][bc] = b4n;
            __syncthreads();
        }
    }

#pragma unroll
    for (int i = 0; i < 8; i++) {
        int rr = row0 + ty * 8 + i;
        if (rr >= M) continue;
        {
            float v0 = acc[i][0], v1 = acc[i][1], v2 = acc[i][2], v3 = acc[i][3];
            if (MODE == 1) {
                int c = col0 + tx * 4;
                v0 = tanhf(v0 + bias[c + 0]); v1 = tanhf(v1 + bias[c + 1]);
                v2 = tanhf(v2 + bias[c + 2]); v3 = tanhf(v3 + bias[c + 3]);
            }
            *(float4*)&C[(size_t)rr * ldc + ccol0 + tx * 4] = make_float4(v0, v1, v2, v3);
        }
        if (MICRO_N == 8) {
            float v0 = acc[i][4], v1 = acc[i][5], v2 = acc[i][6], v3 = acc[i][7];
            if (MODE == 1) {
                int c = col0 + 64 + tx * 4;
                v0 = tanhf(v0 + bias[c + 0]); v1 = tanhf(v1 + bias[c + 1]);
                v2 = tanhf(v2 + bias[c + 2]); v3 = tanhf(v3 + bias[c + 3]);
            }
            *(float4*)&C[(size_t)rr * ldc + ccol0 + 64 + tx * 4] = make_float4(v0, v1, v2, v3);
        }
    }
}

// ---------------- el/er ----------------
__global__ void compute_lr(const float* __restrict__ attn_l, const float* __restrict__ attn_r)
{
    int idx = blockIdx.x * blockDim.x + threadIdx.x;   // (p*N+n)*8 + h
    if (idx >= Pp * Nn * Hh) return;
    int h = idx & 7;
    int n = (idx >> 3) % Nn;
    int p = idx / (Nn * Hh);
    const float4* w  = (const float4*)(g_Wh + (size_t)n * PHD + p * HDs + h * Dd);
    const float4* al = (const float4*)(attn_l + (p * Hh + h) * Dd);
    const float4* ar = (const float4*)(attn_r + (p * Hh + h) * Dd);
    float sl = 0.f, sr = 0.f;
#pragma unroll
    for (int i = 0; i < 16; i++) {
        float4 wv = w[i], a = al[i], b = ar[i];
        sl += wv.x * a.x + wv.y * a.y + wv.z * a.z + wv.w * a.w;
        sr += wv.x * b.x + wv.y * b.y + wv.z * b.z + wv.w * b.w;
    }
    g_el[idx] = sl;
    g_er[idx] = sr;
}

// ---------------- CSR build ----------------
__global__ void hist_k(const int* __restrict__ edst)
{
    int idx = blockIdx.x * blockDim.x + threadIdx.x;
    if (idx >= Pp * Ee) return;
    int p = idx / Ee;
    atomicAdd(&g_cur[p * Nn + edst[idx]], 1);
}

__global__ void scan_k()   // one block per path; warp-shuffle scan
{
    __shared__ int wsum[32];
    const int p = blockIdx.x, tid = threadIdx.x;
    const int lane = tid & 31, wid = tid >> 5;
    int base = 0;
    for (int c0 = 0; c0 < Nn; c0 += 1024) {
        int i = c0 + tid;
        int v = (i < Nn) ? g_cur[p * Nn + i] : 0;
        int x = v;
#pragma unroll
        for (int o = 1; o < 32; o <<= 1) {
            int t = __shfl_up_sync(0xffffffffu, x, o);
            if (lane >= o) x += t;
        }
        if (lane == 31) wsum[wid] = x;
        __syncthreads();
        if (wid == 0) {
            int w = wsum[lane];
#pragma unroll
            for (int o = 1; o < 32; o <<= 1) {
                int t = __shfl_up_sync(0xffffffffu, w, o);
                if (lane >= o) w += t;
            }
            wsum[lane] = w;
        }
        __syncthreads();
        int add = (wid > 0) ? wsum[wid - 1] : 0;
        int incl = base + add + x;
        if (i < Nn) {
            g_cur[p * Nn + i] = incl - v;                 // exclusive
            g_off[p * (Nn + 1) + i + 1] = incl;
        }
        if (i == 0) g_off[p * (Nn + 1)] = 0;
        base += wsum[31];
        __syncthreads();
    }
}

__global__ void scatter_k(const int* __restrict__ esrc, const int* __restrict__ edst)
{
    int idx = blockIdx.x * blockDim.x + threadIdx.x;
    if (idx >= Pp * Ee) return;
    int p = idx / Ee;
    int d = edst[idx];
    int pos = atomicAdd(&g_cur[p * Nn + d], 1);
    g_srcs[p * Ee + pos] = esrc[idx];
}

// ---------------- warp-per-dst: logits + online softmax + aggregation + elu ----------------
__global__ void attn_agg_k(const float* __restrict__ gat_b)
{
    const int warpsPerBlock = blockDim.x >> 5;
    const int gw = blockIdx.x * warpsPerBlock + (threadIdx.x >> 5);
    if (gw >= Pp * Nn) return;
    const int lane = threadIdx.x & 31;
    const int p = gw / Nn, n = gw % Nn;
    const int beg = g_off[p * (Nn + 1) + n];
    const int end = g_off[p * (Nn + 1) + n + 1];
    const int sub = lane & 7;
    const int* srcs = g_srcs + (size_t)p * Ee;
    const float* el = g_el + (size_t)p * Nn * 8;

    const float erh = g_er[(size_t)(p * Nn + n) * 8 + sub];

    // pass A: per-head max (4 edges in parallel, 8 lanes/edge)
    float m = -1e30f;
    for (int k = beg + (lane >> 3); k < end; k += 4) {
        int s = srcs[k];
        float v = el[(size_t)s * 8 + sub] + erh;
        v = v > 0.f ? v : 0.2f * v;
        m = fmaxf(m, v);
    }
    m = fmaxf(m, __shfl_xor_sync(0xffffffffu, m, 8));
    m = fmaxf(m, __shfl_xor_sync(0xffffffffu, m, 16));

    // pass B: fused exp-sum + unnormalized weighted aggregate
    float4 acc[4];
#pragma unroll
    for (int j = 0; j < 4; j++) acc[j] = make_float4(0.f, 0.f, 0.f, 0.f);
    float ssum = 0.f;

    const int hsel = lane >> 4;   // 0 or 1
    for (int k = beg; k < end; ++k) {
        int s = srcs[k];                                   // uniform load
        float v = el[(size_t)s * 8 + sub] + erh;           // 32B line per edge
        v = v > 0.f ? v : 0.2f * v;
        float a8 = expf(v - m);
        ssum += a8;                                        // head 'sub' partial (dup x4, harmless)
        const float4* wr = (const float4*)(g_Wh + (size_t)s * PHD + p * HDs);
#pragma unroll
        for (int j = 0; j < 4; j++) {
            float a = __shfl_sync(0xffffffffu, a8, 2 * j + hsel);
            float4 w4 = wr[j * 32 + lane];
            acc[j].x += a * w4.x; acc[j].y += a * w4.y;
            acc[j].z += a * w4.z; acc[j].w += a * w4.w;
        }
    }
    float inv = (ssum > 0.f) ? 1.f / ssum : 0.f;           // valid for head 'sub'

    // epilogue: normalize, + bias, elu, write z
    float* zr = g_z + (size_t)n * PHD + p * HDs;
    const float* br = gat_b + p * HDs;
#pragma unroll
    for (int j = 0; j < 4; j++) {
        float invh = __shfl_sync(0xffffffffu, inv, 2 * j + hsel);
        int col = 128 * j + 4 * lane;
        float4 b4 = *(const float4*)&br[col];
        float x0 = acc[j].x * invh + b4.x;
        float x1 = acc[j].y * invh + b4.y;
        float x2 = acc[j].z * invh + b4.z;
        float x3 = acc[j].w * invh + b4.w;
        x0 = x0 > 0.f ? x0 : expm1f(x0);
        x1 = x1 > 0.f ? x1 : expm1f(x1);
        x2 = x2 > 0.f ? x2 : expm1f(x2);
        x3 = x3 > 0.f ? x3 : expm1f(x3);
        *(float4*)&zr[col] = make_float4(x0, x1, x2, x3);
    }
}

// ---------------- semantic attention tail ----------------
__global__ void score_k(const float* __restrict__ W2)
{
    int gw = blockIdx.x * (blockDim.x >> 5) + (threadIdx.x >> 5);
    if (gw >= Nn * Pp) return;
    int lane = threadIdx.x & 31;
    float v = g_T[(size_t)gw * 64 + lane] * W2[lane] +
              g_T[(size_t)gw * 64 + lane + 32] * W2[lane + 32];
#pragma unroll
    for (int ofs = 16; ofs > 0; ofs >>= 1)
        v += __shfl_xor_sync(0xffffffffu, v, ofs);
    if (lane == 0) g_scores[gw] = v;
}

__global__ void reduce_k()
{
    __shared__ float sh[256];
    int p = blockIdx.x, tid = threadIdx.x;
    float s = 0.f;
    for (int n = tid; n < Nn; n += 256) s += g_scores[(size_t)n * Pp + p];
    sh[tid] = s;
    __syncthreads();
    for (int ofs = 128; ofs > 0; ofs >>= 1) {
        if (tid < ofs) sh[tid] += sh[tid + ofs];
        __syncthreads();
    }
    if (tid == 0) g_wsum[p] = sh[0];
}

__global__ void beta_k()
{
    if (threadIdx.x == 0 && blockIdx.x == 0) {
        float w[Pp], mx = -1e30f;
        for (int p = 0; p < Pp; p++) { w[p] = g_wsum[p] / (float)Nn; mx = fmaxf(mx, w[p]); }
        float ssum = 0.f;
        for (int p = 0; p < Pp; p++) { w[p] = expf(w[p] - mx); ssum += w[p]; }
        for (int p = 0; p < Pp; p++) g_beta[p] = w[p] / ssum;
    }
}

__global__ void combine_k(float* __restrict__ out)
{
    int idx = blockIdx.x * blockDim.x + threadIdx.x;  // float4 index
    if (idx >= Nn * HDs / 4) return;
    int n = idx / (HDs / 4);
    int c4 = (idx % (HDs / 4)) * 4;
    float b0 = g_beta[0], b1 = g_beta[1], b2 = g_beta[2], b3 = g_beta[3];
    const float* zr = g_z + (size_t)n * PHD;
    float4 v0 = *(const float4*)&zr[0 * HDs + c4];
    float4 v1 = *(const float4*)&zr[1 * HDs + c4];
    float4 v2 = *(const float4*)&zr[2 * HDs + c4];
    float4 v3 = *(const float4*)&zr[3 * HDs + c4];
    float4 o;
    o.x = b0 * v0.x + b1 * v1.x + b2 * v2.x + b3 * v3.x;
    o.y = b0 * v0.y + b1 * v1.y + b2 * v2.y + b3 * v3.y;
    o.z = b0 * v0.z + b1 * v1.z + b2 * v2.z + b3 * v3.z;
    o.w = b0 * v0.w + b1 * v1.w + b2 * v2.w + b3 * v3.w;
    *(float4*)&((float*)out)[(size_t)n * HDs + c4] = o;
}

// ---------------- launch ----------------
extern "C" void kernel_launch(void* const* d_in, const int* in_sizes, int n_in,
                              void* d_out, int out_size)
{
    const float* h        = (const float*)d_in[0];
    const int*   edge_src = (const int*)  d_in[1];
    const int*   edge_dst = (const int*)  d_in[2];
    const float* gat_W    = (const float*)d_in[3];
    const float* attn_l   = (const float*)d_in[4];
    const float* attn_r   = (const float*)d_in[5];
    const float* gat_b    = (const float*)d_in[6];
    const float* sem_W1   = (const float*)d_in[7];
    const float* sem_b1   = (const float*)d_in[8];
    const float* sem_W2   = (const float*)d_in[9];
    float* out = (float*)d_out;

    void *pWh, *pZ, *pT, *pCur;
    cudaGetSymbolAddress(&pWh, g_Wh);
    cudaGetSymbolAddress(&pZ,  g_z);
    cudaGetSymbolAddress(&pT,  g_T);
    cudaGetSymbolAddress(&pCur, g_cur);

    // CSR build
    cudaMemsetAsync(pCur, 0, Pp * Nn * sizeof(int));
    hist_k<<<(Pp * Ee + 255) / 256, 256>>>(edge_dst);
    scan_k<<<Pp, 1024>>>();
    scatter_k<<<(Pp * Ee + 255) / 256, 256>>>(edge_src, edge_dst);

    // 1) Wh[p] = h @ gat_W[p] for all p in one launch
    sgemm_t<128, 0><<<dim3(HDs / 128, (Nn + 127) / 128, Pp), 256>>>(
        h, gat_W, (float*)pWh, nullptr,
        Nn, INs, INs, HDs, PHD, (long)INs * HDs, HDs);

    // 2) el/er
    compute_lr<<<(Pp * Nn * Hh + 255) / 256, 256>>>(attn_l, attn_r);

    // 3) softmax + aggregate + elu -> g_z
    attn_agg_k<<<(Pp * Nn + 7) / 8, 256>>>(gat_b);

    // 4) T = tanh(Z @ W1 + b1)
    sgemm_t<64, 1><<<dim3(1, (Nn * Pp + 127) / 128, 1), 256>>>(
        (const float*)pZ, sem_W1, (float*)pT, sem_b1,
        Nn * Pp, HDs, HDs, 64, 64, 0L, 0);

    // 5) scores, per-path mean, softmax, combine
    score_k<<<(Nn * Pp + 7) / 8, 256>>>(sem_W2);
    reduce_k<<<Pp, 256>>>();
    beta_k<<<1, 32>>>();
    combine_k<<<(Nn * HDs / 4 + 255) / 256, 256>>>(out);
}